// round 13
// baseline (speedup 1.0000x reference)
#include <cuda_runtime.h>
#include <cuda_bf16.h>

// RecNN DAG evaluation — only outputs[N-1] matters; out is LINEAR in the
// terminal values, so propagate coefficients top-down:
//   out = (sum_t coef_t * values[t]) * w_term * w_final + b_final
//
// R9: register-resident frontier + warp-shuffle redistribution.
//  - internal/ballot/routing (__fns) depend only on idx -> fully overlap the
//    child_idx LDG latency; only 4 shuffles sit on the chase chain.
//  - base = idx - W (levels are W-strided), pre-folded into base pointers.
//  - smem spill stack only when frontier > 32 lanes (uniform, rare).
//
// Inputs (metadata order):
//   d_in[0] values     float[L*W]
//   d_in[1] child_idx  int[(L-1)*W*2]
//   d_in[2] node_types int[(L-1)*W]
//   d_in[3] w_term float[1]  d_in[4] w_plus float[2]  d_in[5] w_minus float[2]
//   d_in[6] w_final float[1] d_in[7] b_final float[1]
// Output: float[1]

#define RN_L 32
#define RN_W 262144            // 2^18
#define RN_N (RN_L * RN_W)
#define STK  512               // spill stack (tree ~100 nodes; big margin)

__global__ void __launch_bounds__(32, 1)
recnn_shfl_kernel(const float* __restrict__ values,
                  const int*   __restrict__ child_idx,
                  const int*   __restrict__ node_types,
                  const float* __restrict__ w_term,
                  const float* __restrict__ w_plus,
                  const float* __restrict__ w_minus,
                  const float* __restrict__ w_final,
                  const float* __restrict__ b_final,
                  float*       __restrict__ out)
{
    __shared__ __align__(8) int2 stk[STK];   // (node_idx, coef bits)

    const int      lane = threadIdx.x;
    const unsigned FULL = 0xffffffffu;
    const unsigned lt   = (1u << lane) - 1u;

    const float wp0 = __ldg(w_plus),  wp1 = __ldg(w_plus + 1);
    const float wm0 = __ldg(w_minus), wm1 = __ldg(w_minus + 1);

    // level-(l) node idx maps to row (idx - W) in child_idx/node_types
    const int2* __restrict__ cbase = reinterpret_cast<const int2*>(child_idx) - RN_W;
    const int*  __restrict__ tbase = node_types - RN_W;

    float acc   = 0.0f;
    bool  valid = (lane == 0);
    int   idx   = RN_N - 1;       // root
    float coef  = 1.0f;
    int   S     = 0;              // spill-stack depth (uniform)

    for (;;) {
        // routing info depends only on idx -> overlaps the LDG below
        const bool     internal = valid && (idx >= RN_W);
        const unsigned m        = __ballot_sync(FULL, internal);
        const int      nch      = 2 * __popc(m);

        int2  ch  = make_int2(0, 0);
        float cw0 = 0.0f, cw1 = 0.0f;
        if (internal) {
            ch = __ldg(cbase + idx);                 // the pointer-chase load
            const int typ = __ldg(tbase + idx);      // parallel to ch
            cw0 = coef * ((typ == 1) ? wp0 : wm0);
            cw1 = coef * ((typ == 1) ? wp1 : wm1);
        } else if (valid) {
            acc += coef * __ldg(values + idx);       // terminal (off-chain)
        }

        if ((nch | S) == 0) break;

        // lane j takes child j: parent = rank j>>1 among set bits of m
        const bool take = lane < nch;
        const int  src  = take ? __fns(m, 0, (lane >> 1) + 1) : 0;
        const int   gx = __shfl_sync(FULL, ch.x, src);
        const int   gy = __shfl_sync(FULL, ch.y, src);
        const float g0 = __shfl_sync(FULL, cw0,  src);
        const float g1 = __shfl_sync(FULL, cw1,  src);

        // overflow push (only possible when nch > 32)
        int push = nch - 32; if (push < 0) push = 0;
        if (push > 0 && internal) {
            const int p  = __popc(m & lt);
            const int j0 = 2 * p, j1 = j0 + 1;
            if (j0 >= 32) stk[S + j0 - 32] = make_int2(ch.x, __float_as_int(cw0));
            if (j1 >= 32) stk[S + j1 - 32] = make_int2(ch.y, __float_as_int(cw1));
        }
        const int avail = 32 - (nch < 32 ? nch : 32);
        const int npop  = (S < avail) ? S : avail;

        bool  nvalid = false;
        int   nidx   = 0;
        float ncoef  = 0.0f;
        if (take) {
            nvalid = true;
            nidx   = (lane & 1) ? gy : gx;
            ncoef  = (lane & 1) ? g1 : g0;
        } else {
            const int pi = lane - nch;
            if (pi < npop) {                         // refill from spill stack
                const int2 e = stk[S - 1 - pi];
                nidx = e.x; ncoef = __int_as_float(e.y); nvalid = true;
            }
        }
        S += push - npop;
        if (push > 0) __syncwarp();                  // uniform; rare

        valid = nvalid; idx = nidx; coef = ncoef;
    }

    // deterministic warp reduction of the terminal accumulator
    #pragma unroll
    for (int o = 16; o > 0; o >>= 1)
        acc += __shfl_xor_sync(FULL, acc, o);

    if (lane == 0)
        out[0] = acc * __ldg(w_term) * __ldg(w_final) + __ldg(b_final);
}

extern "C" void kernel_launch(void* const* d_in, const int* in_sizes, int n_in,
                              void* d_out, int out_size)
{
    const float* values     = (const float*)d_in[0];
    const int*   child_idx  = (const int*)  d_in[1];
    const int*   node_types = (const int*)  d_in[2];
    const float* w_term     = (const float*)d_in[3];
    const float* w_plus     = (const float*)d_in[4];
    const float* w_minus    = (const float*)d_in[5];
    const float* w_final    = (const float*)d_in[6];
    const float* b_final    = (const float*)d_in[7];
    float* out = (float*)d_out;

    recnn_shfl_kernel<<<1, 32>>>(values, child_idx, node_types,
                                 w_term, w_plus, w_minus,
                                 w_final, b_final, out);
}

// round 14
// speedup vs baseline: 2.2103x; 2.2103x over previous
#include <cuda_runtime.h>
#include <cuda_bf16.h>

// RecNN DAG evaluation — only outputs[N-1] matters; out is LINEAR in the
// terminal values, so propagate coefficients top-down:
//   out = (sum_t coef_t * values[t]) * w_term * w_final + b_final
//
// R13: smem-frontier BFS (R8 structure, best so far) with the pointer chase
// UNROLLED 2 LEVELS per round: after the child record arrives, both
// grandchild records load in parallel (one extra serial hop covers two
// levels), so LDS/sync/ballot overhead is paid once per 2 levels. The
// frontier stores internal nodes only — terminals are folded into acc
// inline (off the chase chain), removing trailing rounds.
//
// Inputs (metadata order):
//   d_in[0] values     float[L*W]
//   d_in[1] child_idx  int[(L-1)*W*2]
//   d_in[2] node_types int[(L-1)*W]
//   d_in[3] w_term float[1]  d_in[4] w_plus float[2]  d_in[5] w_minus float[2]
//   d_in[6] w_final float[1] d_in[7] b_final float[1]
// Output: float[1]

#define RN_L 32
#define RN_W 262144            // 2^18
#define RN_N (RN_L * RN_W)
#define MAX_NODES 4096         // tree ~100 nodes; huge margin

__global__ void __launch_bounds__(32, 1)
recnn_u2_kernel(const float* __restrict__ values,
                const int*   __restrict__ child_idx,
                const int*   __restrict__ node_types,
                const float* __restrict__ w_term,
                const float* __restrict__ w_plus,
                const float* __restrict__ w_minus,
                const float* __restrict__ w_final,
                const float* __restrict__ b_final,
                float*       __restrict__ out)
{
    __shared__ __align__(8) int2 fr[MAX_NODES];   // (internal node idx, coef)

    const int      lane = threadIdx.x;
    const unsigned FULL = 0xffffffffu;
    const unsigned lt   = (1u << lane) - 1u;

    const float wp0 = __ldg(w_plus),  wp1 = __ldg(w_plus + 1);
    const float wm0 = __ldg(w_minus), wm1 = __ldg(w_minus + 1);

    // level-l node idx maps to row (idx - W) of child_idx / node_types
    const int2* __restrict__ cbase = reinterpret_cast<const int2*>(child_idx) - RN_W;
    const int*  __restrict__ tbase = node_types - RN_W;

    float acc = 0.0f;

    if (lane == 0)
        fr[0] = make_int2(RN_N - 1, __float_as_int(1.0f));   // root (internal)
    __syncwarp();

    int lo = 0, hi = 1, wpos = 1;

    while (lo < hi) {
        for (int cb = lo; cb < hi; cb += 32) {
            const int  slot = cb + lane;
            const bool v    = slot < hi;

            int   idx  = 0;
            float coef = 0.0f;
            if (v) {
                const int2 f = fr[slot];
                idx  = f.x;
                coef = __int_as_float(f.y);
            }

            // ---- level 1: this node's record (chase hop 1) ----
            int2 ch  = make_int2(0, 0);
            int  typ = 1;
            if (v) {
                ch  = __ldg(cbase + idx);
                typ = __ldg(tbase + idx);      // parallel to ch
            }
            const float cw0 = coef * ((typ == 1) ? wp0 : wm0);
            const float cw1 = coef * ((typ == 1) ? wp1 : wm1);

            // ---- level 2: grandchild records (chase hop 2, A ∥ B) ----
            const bool iA = v && (ch.x >= RN_W);
            const bool iB = v && (ch.y >= RN_W);
            int2 gA = make_int2(0, 0), gB = make_int2(0, 0);
            int  tA = 1, tB = 1;
            if (iA) { gA = __ldg(cbase + ch.x); tA = __ldg(tbase + ch.x); }
            else if (v) acc += cw0 * __ldg(values + ch.x);      // terminal child
            if (iB) { gB = __ldg(cbase + ch.y); tB = __ldg(tbase + ch.y); }
            else if (v) acc += cw1 * __ldg(values + ch.y);      // terminal child

            const float aw0 = cw0 * ((tA == 1) ? wp0 : wm0);
            const float aw1 = cw0 * ((tA == 1) ? wp1 : wm1);
            const float bw0 = cw1 * ((tB == 1) ? wp0 : wm0);
            const float bw1 = cw1 * ((tB == 1) ? wp1 : wm1);

            // four potential frontier entries (grandchildren that are internal)
            const bool e0 = iA && (gA.x >= RN_W);
            const bool e1 = iA && (gA.y >= RN_W);
            const bool e2 = iB && (gB.x >= RN_W);
            const bool e3 = iB && (gB.y >= RN_W);

            // terminal grandchildren folded into acc (off-chain)
            if (iA && !e0) acc += aw0 * __ldg(values + gA.x);
            if (iA && !e1) acc += aw1 * __ldg(values + gA.y);
            if (iB && !e2) acc += bw0 * __ldg(values + gB.x);
            if (iB && !e3) acc += bw1 * __ldg(values + gB.y);

            // compact the internal grandchildren into the frontier
            const unsigned m0 = __ballot_sync(FULL, e0);
            const unsigned m1 = __ballot_sync(FULL, e1);
            const unsigned m2 = __ballot_sync(FULL, e2);
            const unsigned m3 = __ballot_sync(FULL, e3);
            const int c0 = __popc(m0), c1 = __popc(m1);
            const int c2 = __popc(m2), c3 = __popc(m3);

            const int p0 = wpos + __popc(m0 & lt);
            const int p1 = wpos + c0 + __popc(m1 & lt);
            const int p2 = wpos + c0 + c1 + __popc(m2 & lt);
            const int p3 = wpos + c0 + c1 + c2 + __popc(m3 & lt);

            if (e0 && p0 < MAX_NODES) fr[p0] = make_int2(gA.x, __float_as_int(aw0));
            if (e1 && p1 < MAX_NODES) fr[p1] = make_int2(gA.y, __float_as_int(aw1));
            if (e2 && p2 < MAX_NODES) fr[p2] = make_int2(gB.x, __float_as_int(bw0));
            if (e3 && p3 < MAX_NODES) fr[p3] = make_int2(gB.y, __float_as_int(bw1));

            wpos += c0 + c1 + c2 + c3;          // uniform across lanes
        }
        __syncwarp();
        lo = hi;
        hi = wpos;
    }

    // deterministic warp reduction of the terminal accumulator
    #pragma unroll
    for (int o = 16; o > 0; o >>= 1)
        acc += __shfl_xor_sync(FULL, acc, o);

    if (lane == 0)
        out[0] = acc * __ldg(w_term) * __ldg(w_final) + __ldg(b_final);
}

extern "C" void kernel_launch(void* const* d_in, const int* in_sizes, int n_in,
                              void* d_out, int out_size)
{
    const float* values     = (const float*)d_in[0];
    const int*   child_idx  = (const int*)  d_in[1];
    const int*   node_types = (const int*)  d_in[2];
    const float* w_term     = (const float*)d_in[3];
    const float* w_plus     = (const float*)d_in[4];
    const float* w_minus    = (const float*)d_in[5];
    const float* w_final    = (const float*)d_in[6];
    const float* b_final    = (const float*)d_in[7];
    float* out = (float*)d_out;

    recnn_u2_kernel<<<1, 32>>>(values, child_idx, node_types,
                               w_term, w_plus, w_minus,
                               w_final, b_final, out);
}